// round 2
// baseline (speedup 1.0000x reference)
#include <cuda_runtime.h>
#include <cstdint>

#define BS 4
#define SQ 1024
#define CH 64
#define UN 32
#define TSPAN 72   // 8 query rows + 64 window

__device__ float g_q[BS * SQ * UN];
__device__ float g_k[BS * SQ * UN];

__device__ __forceinline__ float htanh(float x) {
    float y;
    asm("tanh.approx.f32 %0, %1;" : "=f"(y) : "f"(x));
    return y;
}

// ---------------------------------------------------------------------------
// Kernel 1: q[b,s,u] = sum_c x[b,c,s]*Wt[u,c];  k[b,s,u] = sum_c x*Wx + bh[u]
// block = 256 threads, handles (b, 32 consecutive s). grid = 4*32 = 128.
// 2x2 register tiling per thread: 16x16 thread grid covers 32(u) x 32(s).
// ---------------------------------------------------------------------------
__global__ __launch_bounds__(256) void qk_kernel(const float* __restrict__ x,
                                                 const float* __restrict__ Wt,
                                                 const float* __restrict__ Wx,
                                                 const float* __restrict__ bh) {
    __shared__ __align__(16) float xs[CH * 36];   // [c][j], j<32, pad 36
    __shared__ __align__(16) float wts[CH * 36];  // [c][u]
    __shared__ __align__(16) float wxs[CH * 36];
    __shared__ float bhs[UN];

    int b = blockIdx.x >> 5;
    int s0 = (blockIdx.x & 31) << 5;
    int tid = threadIdx.x;

    for (int lin = tid; lin < CH * 32; lin += 256) {
        int c = lin >> 5, j = lin & 31;
        xs[c * 36 + j] = x[(size_t)b * CH * SQ + c * SQ + s0 + j];
    }
    for (int lin = tid; lin < UN * CH; lin += 256) {
        int u = lin >> 6, c = lin & 63;
        wts[c * 36 + u] = Wt[lin];
        wxs[c * 36 + u] = Wx[lin];
    }
    if (tid < UN) bhs[tid] = bh[tid];
    __syncthreads();

    int u0 = (tid & 15) * 2;   // 0..30
    int j0 = (tid >> 4) * 2;   // 0..30
    float qa[2][2] = {};
    float ka[2][2] = {};
#pragma unroll 8
    for (int c = 0; c < CH; c++) {
        float2 xv = *(const float2*)&xs[c * 36 + j0];
        float2 wt = *(const float2*)&wts[c * 36 + u0];
        float2 wx = *(const float2*)&wxs[c * 36 + u0];
        float xr[2] = {xv.x, xv.y};
        float wtr[2] = {wt.x, wt.y};
        float wxr[2] = {wx.x, wx.y};
#pragma unroll
        for (int r = 0; r < 2; r++) {
#pragma unroll
            for (int uu = 0; uu < 2; uu++) {
                qa[r][uu] = fmaf(xr[r], wtr[uu], qa[r][uu]);
                ka[r][uu] = fmaf(xr[r], wxr[uu], ka[r][uu]);
            }
        }
    }
#pragma unroll
    for (int r = 0; r < 2; r++) {
        size_t base = ((size_t)b * SQ + s0 + j0 + r) * UN + u0;
#pragma unroll
        for (int uu = 0; uu < 2; uu++) {
            g_q[base + uu] = qa[r][uu];
            g_k[base + uu] = ka[r][uu] + bhs[u0 + uu];  // fold bh into k
        }
    }
}

// ---------------------------------------------------------------------------
// Kernel 2: per query row s (one warp each; 8 rows/block, grid = 4*128 = 512):
//   scores over the 64-wide window, window softmax (+eps), write full a row
//   (zeros outside window), then v[s,c] = sum_t a * x[b,c,t] -> v[b,c,s].
// Wa_b dropped (cancels exactly in softmax). Window max used instead of full
// row max (error <= ~1e-6 through eps; softmax shift otherwise cancels).
// ---------------------------------------------------------------------------
__global__ __launch_bounds__(256) void attn_kernel(const float* __restrict__ x,
                                                   const float* __restrict__ wa,
                                                   float* __restrict__ vout,
                                                   float* __restrict__ aout) {
    __shared__ __align__(16) float ks[TSPAN * 36];   // [ti][u], pad 36
    __shared__ __align__(16) float xts[TSPAN * 66];  // [ti][c], pad 66
    __shared__ __align__(16) float qs[8 * 32];       // [w][u]
    __shared__ __align__(16) float a_s[8 * 64];      // [w][j]
    __shared__ __align__(16) float was[UN];
    __shared__ float vs[CH * 9];                     // [c][w], pad 9

    int b = blockIdx.x >> 7;
    int s0 = (blockIdx.x & 127) << 3;
    int tid = threadIdx.x;
    int w = tid >> 5, ln = tid & 31;
    int tlo = s0 - 32;

    if (tid < UN) was[tid] = wa[tid];
    qs[tid] = g_q[((size_t)b * SQ + s0 + w) * UN + ln];
    for (int lin = tid; lin < TSPAN * UN; lin += 256) {
        int ti = lin >> 5, u = lin & 31;
        int t = tlo + ti;
        ks[ti * 36 + u] = (t >= 0 && t < SQ) ? g_k[((size_t)b * SQ + t) * UN + u] : 0.f;
    }
    for (int lin = tid; lin < TSPAN * CH; lin += 256) {
        int c = lin / TSPAN, ti = lin - c * TSPAN;
        int t = tlo + ti;
        xts[ti * 66 + c] = (t >= 0 && t < SQ) ? x[(size_t)b * CH * SQ + c * SQ + t] : 0.f;
    }
    __syncthreads();

    int s = s0 + w;
    // lane handles window offsets j = ln and j = ln+32; t = s-32+j
    int t1 = s - 32 + ln;   // in [s-32, s-1]  -> always < SQ
    int t2 = t1 + 32;       // in [s,   s+31]  -> always >= 0
    bool val1 = (t1 >= 0);
    bool val2 = (t2 < SQ);

    const float4* k1p = (const float4*)&ks[(w + ln) * 36];
    const float4* k2p = (const float4*)&ks[(w + ln + 32) * 36];
    const float4* qp = (const float4*)&qs[w * 32];
    const float4* wap = (const float4*)was;
    float acc1 = 0.f, acc2 = 0.f;
#pragma unroll
    for (int g = 0; g < 8; g++) {
        float4 q4 = qp[g];
        float4 w4 = wap[g];
        float4 ka = k1p[g];
        float4 kb = k2p[g];
        acc1 = fmaf(w4.x, htanh(q4.x + ka.x), acc1);
        acc1 = fmaf(w4.y, htanh(q4.y + ka.y), acc1);
        acc1 = fmaf(w4.z, htanh(q4.z + ka.z), acc1);
        acc1 = fmaf(w4.w, htanh(q4.w + ka.w), acc1);
        acc2 = fmaf(w4.x, htanh(q4.x + kb.x), acc2);
        acc2 = fmaf(w4.y, htanh(q4.y + kb.y), acc2);
        acc2 = fmaf(w4.z, htanh(q4.z + kb.z), acc2);
        acc2 = fmaf(w4.w, htanh(q4.w + kb.w), acc2);
    }
    float sc1 = val1 ? acc1 : -1e30f;
    float sc2 = val2 ? acc2 : -1e30f;
    float m = fmaxf(sc1, sc2);
#pragma unroll
    for (int o = 16; o > 0; o >>= 1) m = fmaxf(m, __shfl_xor_sync(0xffffffffu, m, o));
    float e1 = val1 ? __expf(sc1 - m) : 0.f;
    float e2 = val2 ? __expf(sc2 - m) : 0.f;
    float sm = e1 + e2;
#pragma unroll
    for (int o = 16; o > 0; o >>= 1) sm += __shfl_xor_sync(0xffffffffu, sm, o);
    float inv = __fdividef(1.f, sm + 1e-7f);
    a_s[(w << 6) + ln] = e1 * inv;
    a_s[(w << 6) + ln + 32] = e2 * inv;
    __syncwarp();

    // full a row write: zeros outside window, coalesced float4
    float4* arow = (float4*)(aout + (((size_t)b * SQ + s) << 10));
#pragma unroll
    for (int i = 0; i < 8; i++) {
        int col = (i << 7) + (ln << 2);
        int j = col - s + 32;
        float4 val;
        val.x = ((unsigned)(j + 0) < 64u) ? a_s[(w << 6) + j + 0] : 0.f;
        val.y = ((unsigned)(j + 1) < 64u) ? a_s[(w << 6) + j + 1] : 0.f;
        val.z = ((unsigned)(j + 2) < 64u) ? a_s[(w << 6) + j + 2] : 0.f;
        val.w = ((unsigned)(j + 3) < 64u) ? a_s[(w << 6) + j + 3] : 0.f;
        arow[(i << 5) + ln] = val;
    }

    // v[s, c] = sum_j a[s,j] * xt[t(j), c];  lane owns c = 2*ln, 2*ln+1
    float ax = 0.f, ay = 0.f;
#pragma unroll 8
    for (int j = 0; j < 64; j++) {
        float av = a_s[(w << 6) + j];
        float2 xv = *(const float2*)&xts[(w + j) * 66 + (ln << 1)];
        ax = fmaf(av, xv.x, ax);
        ay = fmaf(av, xv.y, ay);
    }
    vs[(ln * 2) * 9 + w] = ax;
    vs[(ln * 2 + 1) * 9 + w] = ay;
    __syncthreads();

    // coalesced transposed v output: v[b][c][s0..s0+8)
    for (int lin = tid; lin < CH * 8; lin += 256) {
        int c = lin >> 3, i = lin & 7;
        vout[(size_t)b * CH * SQ + c * SQ + s0 + i] = vs[c * 9 + i];
    }
}

extern "C" void kernel_launch(void* const* d_in, const int* in_sizes, int n_in,
                              void* d_out, int out_size) {
    (void)in_sizes; (void)n_in; (void)out_size;
    const float* x  = (const float*)d_in[0];
    const float* Wt = (const float*)d_in[1];
    const float* Wx = (const float*)d_in[2];
    const float* Wa = (const float*)d_in[3];
    // d_in[4] = Wa_b: cancels exactly in the softmax, unused
    const float* bh = (const float*)d_in[5];

    float* vout = (float*)d_out;                     // (B, C, S)
    float* aout = vout + (size_t)BS * CH * SQ;       // (B, S, S)

    qk_kernel<<<BS * 32, 256>>>(x, Wt, Wx, bh);
    attn_kernel<<<BS * 128, 256>>>(x, Wa, vout, aout);
}